// round 4
// baseline (speedup 1.0000x reference)
#include <cuda_runtime.h>
#include <cuda_bf16.h>
#include <math.h>

// Problem constants (fixed by the dataset): B=2, H=16, S=2048, D=64
#define Bn    2
#define Hn    16
#define Sn    2048
#define Dn    64
#define BM    64          // query rows per CTA
#define BN    64          // key cols per tile
#define LDS_  68          // smem row stride in floats (pad vs 64)
#define NTHR  256

#define NEGF  (-3.402823466e38f)

// dynamic smem layout: Qs[D][LDS_] (Q^T), Ks[D][LDS_] (K^T), Vs[BN][LDS_], Ps[BN][LDS_] (P^T)
#define SMEM_FLOATS (4 * Dn * LDS_)
#define SMEM_BYTES  (SMEM_FLOATS * sizeof(float))

// mask dtype mode: 0 = uint8/bool bytes, 1 = int32 0/1, 2 = float32 0.0/1.0
__device__ int g_mask_mode;

__global__ void probe_mask_kernel(const unsigned int* __restrict__ m)
{
    __shared__ int s_i32ok, s_f32ok;
    if (threadIdx.x == 0) { s_i32ok = 1; s_f32ok = 1; }
    __syncthreads();
    int i32ok = 1, f32ok = 1;
    for (int i = threadIdx.x; i < 16384; i += blockDim.x) {
        unsigned int w = m[i];
        if (w > 1u)                          i32ok = 0;
        if (w != 0u && w != 0x3F800000u)     f32ok = 0;
    }
    if (!i32ok) atomicAnd(&s_i32ok, 0);
    if (!f32ok) atomicAnd(&s_f32ok, 0);
    __syncthreads();
    if (threadIdx.x == 0)
        g_mask_mode = s_i32ok ? 1 : (s_f32ok ? 2 : 0);
}

__global__ __launch_bounds__(NTHR)
void attn_fp32_kernel(const float* __restrict__ Q,
                      const float* __restrict__ K,
                      const float* __restrict__ V,
                      const void* __restrict__ Mraw,
                      float* __restrict__ O)
{
    extern __shared__ float sm[];
    float* Qs = sm;                    // [Dn][LDS_]  Qs[d*LDS_+r]
    float* Ks = Qs + Dn * LDS_;        // [Dn][LDS_]  Ks[d*LDS_+c]
    float* Vs = Ks + Dn * LDS_;        // [BN][LDS_]  Vs[c*LDS_+j]
    float* Ps = Vs + BN * LDS_;        // [BN][LDS_]  Ps[c*LDS_+r]

    const int bh  = blockIdx.y;            // b*H + h
    const int b   = bh >> 4;               // H = 16
    const int q0  = blockIdx.x * BM;
    const int tid = threadIdx.x;
    const int tx  = tid & 15;              // 16 column-threads per row group
    const int ty  = tid >> 4;              // 16 row-thread groups
    const int mode = g_mask_mode;          // uniform

    const float* Qg = Q + (size_t)bh * Sn * Dn;
    const float* Kg = K + (size_t)bh * Sn * Dn;
    const float* Vg = V + (size_t)bh * Sn * Dn;
    float* Og = O + (size_t)bh * Sn * Dn;

    const unsigned char* M8  = (const unsigned char*)Mraw + (size_t)b * Sn * Sn;
    const int*           M32 = (const int*)Mraw          + (size_t)b * Sn * Sn;
    const float*         Mf  = (const float*)Mraw        + (size_t)b * Sn * Sn;

    // ---- load Q tile transposed into Qs[d][r] ----
    {
        const int r  = tid >> 2;           // 0..63
        const int dc = (tid & 3) * 16;     // 0,16,32,48
#pragma unroll
        for (int i = 0; i < 4; i++) {
            float4 v = *(const float4*)(Qg + (size_t)(q0 + r) * Dn + dc + i * 4);
            Qs[(dc + i * 4 + 0) * LDS_ + r] = v.x;
            Qs[(dc + i * 4 + 1) * LDS_ + r] = v.y;
            Qs[(dc + i * 4 + 2) * LDS_ + r] = v.z;
            Qs[(dc + i * 4 + 3) * LDS_ + r] = v.w;
        }
    }

    float mrow[4], lrow[4], o[4][4];
#pragma unroll
    for (int i = 0; i < 4; i++) {
        mrow[i] = -INFINITY;
        lrow[i] = 0.f;
#pragma unroll
        for (int j = 0; j < 4; j++) o[i][j] = 0.f;
    }

    for (int kt = 0; kt < Sn; kt += BN) {
        // ---- load K tile transposed (Ks[d][c]) and V tile natural (Vs[c][j]) ----
        {
            const int c  = tid >> 2;
            const int dc = (tid & 3) * 16;
#pragma unroll
            for (int i = 0; i < 4; i++) {
                float4 kv = *(const float4*)(Kg + (size_t)(kt + c) * Dn + dc + i * 4);
                Ks[(dc + i * 4 + 0) * LDS_ + c] = kv.x;
                Ks[(dc + i * 4 + 1) * LDS_ + c] = kv.y;
                Ks[(dc + i * 4 + 2) * LDS_ + c] = kv.z;
                Ks[(dc + i * 4 + 3) * LDS_ + c] = kv.w;
                float4 vv = *(const float4*)(Vg + (size_t)(kt + c) * Dn + dc + i * 4);
                *(float4*)(Vs + c * LDS_ + dc + i * 4) = vv;
            }
        }
        __syncthreads();

        // ---- GEMM1: S = Q K^T  (4x4 per thread) ----
        float s[4][4];
#pragma unroll
        for (int i = 0; i < 4; i++)
#pragma unroll
            for (int j = 0; j < 4; j++) s[i][j] = 0.f;

#pragma unroll 8
        for (int d = 0; d < Dn; d++) {
            const float4 qv = *(const float4*)(Qs + d * LDS_ + (ty << 2));
            const float4 kv = *(const float4*)(Ks + d * LDS_ + (tx << 2));
            s[0][0] += qv.x * kv.x; s[0][1] += qv.x * kv.y; s[0][2] += qv.x * kv.z; s[0][3] += qv.x * kv.w;
            s[1][0] += qv.y * kv.x; s[1][1] += qv.y * kv.y; s[1][2] += qv.y * kv.z; s[1][3] += qv.y * kv.w;
            s[2][0] += qv.z * kv.x; s[2][1] += qv.z * kv.y; s[2][2] += qv.z * kv.z; s[2][3] += qv.z * kv.w;
            s[3][0] += qv.w * kv.x; s[3][1] += qv.w * kv.y; s[3][2] += qv.w * kv.z; s[3][3] += qv.w * kv.w;
        }

        // ---- mask (BEFORE scaling, faithful to reference) then scale ----
        {
            const size_t base = (size_t)(q0 + (ty << 2)) * Sn + kt + (tx << 2);
            if (mode == 1) {
#pragma unroll
                for (int i = 0; i < 4; i++) {
                    int4 mv = *(const int4*)(M32 + base + (size_t)i * Sn);
                    if (mv.x) s[i][0] = NEGF;
                    if (mv.y) s[i][1] = NEGF;
                    if (mv.z) s[i][2] = NEGF;
                    if (mv.w) s[i][3] = NEGF;
                }
            } else if (mode == 0) {
#pragma unroll
                for (int i = 0; i < 4; i++) {
                    uchar4 mv = *(const uchar4*)(M8 + base + (size_t)i * Sn);
                    if (mv.x) s[i][0] = NEGF;
                    if (mv.y) s[i][1] = NEGF;
                    if (mv.z) s[i][2] = NEGF;
                    if (mv.w) s[i][3] = NEGF;
                }
            } else {
#pragma unroll
                for (int i = 0; i < 4; i++) {
                    float4 mv = *(const float4*)(Mf + base + (size_t)i * Sn);
                    if (mv.x != 0.f) s[i][0] = NEGF;
                    if (mv.y != 0.f) s[i][1] = NEGF;
                    if (mv.z != 0.f) s[i][2] = NEGF;
                    if (mv.w != 0.f) s[i][3] = NEGF;
                }
            }
#pragma unroll
            for (int i = 0; i < 4; i++)
#pragma unroll
                for (int j = 0; j < 4; j++) s[i][j] *= 0.125f;   // 1/sqrt(64)
        }

        // ---- online softmax (row groups = 16 consecutive lanes) ----
#pragma unroll
        for (int i = 0; i < 4; i++) {
            float mx = fmaxf(fmaxf(s[i][0], s[i][1]), fmaxf(s[i][2], s[i][3]));
#pragma unroll
            for (int off = 1; off < 16; off <<= 1)
                mx = fmaxf(mx, __shfl_xor_sync(0xffffffffu, mx, off));
            const float mnew = fmaxf(mrow[i], mx);
            const float corr = __expf(mrow[i] - mnew);   // -inf - finite -> 0
            float psum = 0.f;
#pragma unroll
            for (int j = 0; j < 4; j++) {
                float p = __expf(s[i][j] - mnew);
                s[i][j] = p;
                psum += p;
            }
#pragma unroll
            for (int off = 1; off < 16; off <<= 1)
                psum += __shfl_xor_sync(0xffffffffu, psum, off);
            lrow[i] = lrow[i] * corr + psum;
            mrow[i] = mnew;
#pragma unroll
            for (int j = 0; j < 4; j++) {
                o[i][j] *= corr;
            }
        }

        // ---- store P transposed: Ps[c][r] (float4 along r) ----
#pragma unroll
        for (int j = 0; j < 4; j++) {
            *(float4*)(Ps + ((tx << 2) + j) * LDS_ + (ty << 2)) =
                make_float4(s[0][j], s[1][j], s[2][j], s[3][j]);
        }
        __syncthreads();

        // ---- GEMM2: O += P V  (4x4 per thread) ----
#pragma unroll 8
        for (int c = 0; c < BN; c++) {
            const float4 pv = *(const float4*)(Ps + c * LDS_ + (ty << 2));
            const float4 vv = *(const float4*)(Vs + c * LDS_ + (tx << 2));
            o[0][0] += pv.x * vv.x; o[0][1] += pv.x * vv.y; o[0][2] += pv.x * vv.z; o[0][3] += pv.x * vv.w;
            o[1][0] += pv.y * vv.x; o[1][1] += pv.y * vv.y; o[1][2] += pv.y * vv.z; o[1][3] += pv.y * vv.w;
            o[2][0] += pv.z * vv.x; o[2][1] += pv.z * vv.y; o[2][2] += pv.z * vv.z; o[2][3] += pv.z * vv.w;
            o[3][0] += pv.w * vv.x; o[3][1] += pv.w * vv.y; o[3][2] += pv.w * vv.z; o[3][3] += pv.w * vv.w;
        }
        __syncthreads();
    }

    // ---- normalize and write out ----
#pragma unroll
    for (int i = 0; i < 4; i++) {
        const float inv = 1.f / lrow[i];
        float4 r = make_float4(o[i][0] * inv, o[i][1] * inv, o[i][2] * inv, o[i][3] * inv);
        *(float4*)(Og + (size_t)(q0 + (ty << 2) + i) * Dn + (tx << 2)) = r;
    }
}

extern "C" void kernel_launch(void* const* d_in, const int* in_sizes, int n_in,
                              void* d_out, int out_size)
{
    const float* Q = (const float*)d_in[0];
    const float* K = (const float*)d_in[1];
    const float* V = (const float*)d_in[2];
    const void*  M = (const void*)d_in[3];
    float* O = (float*)d_out;

    cudaFuncSetAttribute(attn_fp32_kernel,
                         cudaFuncAttributeMaxDynamicSharedMemorySize, SMEM_BYTES);

    probe_mask_kernel<<<1, 256>>>((const unsigned int*)M);

    dim3 grid(Sn / BM, Bn * Hn);   // (32, 32)
    attn_fp32_kernel<<<grid, NTHR, SMEM_BYTES>>>(Q, K, V, M, O);
}